// round 3
// baseline (speedup 1.0000x reference)
#include <cuda_runtime.h>
#include <cstdint>

#define BATCH 4096
#define MCOLS 4096
#define NROWS 4096
#define NNZ_PER_ROW 819
#define NNZ_TOTAL (NROWS * NNZ_PER_ROW)

#define BM 128
#define BN 128
#define BK 32
#define KSTEPS (MCOLS / BK)        // 128
#define SROW 48                    // smem row stride in floats (192B; 192%128==64 -> conflict-free LDS.128)
#define TILE_FLOATS (128 * SROW)   // 6144 floats (24KB) per matrix per stage
#define STAGE_FLOATS (2 * TILE_FLOATS)      // A+B per stage (48KB)
#define SMEM_BYTES (2 * STAGE_FLOATS * 4)   // double buffered = 98304 B

// Fragment-packed weight + activation buffers. Within each 32-wide k-block,
// element at k = ks*8+km (ks in 0..3, km in 0..7) is stored at km*4+ks, so one
// LDS.128 yields a thread's operand for all 4 k-steps of a k-tile.
// g_Wpack is zero-initialized at module load; scatter writes the same values to
// the same (fixed CSR) positions every call -> deterministic across replays.
__device__ float g_Wpack[(size_t)NROWS * MCOLS];
__device__ float g_Xpack[(size_t)BATCH * MCOLS];

__global__ void scatter_kernel(const float* __restrict__ val,
                               const int* __restrict__ rows,
                               const int* __restrict__ cols) {
    int i = blockIdx.x * blockDim.x + threadIdx.x;
    if (i < NNZ_TOTAL) {
        float v = val[i];
        uint32_t t;
        asm("cvt.rna.tf32.f32 %0, %1;" : "=r"(t) : "f"(v));
        uint32_t c = (uint32_t)cols[i];
        uint32_t off = (c & ~31u) + ((c & 7u) * 4u + ((c >> 3) & 3u));
        g_Wpack[(size_t)rows[i] * MCOLS + off] = __uint_as_float(t);
    }
}

// Pack + tf32-round x. One thread per (row, ktile): permutes a 32-float block.
__global__ void __launch_bounds__(256)
pack_x_kernel(const float* __restrict__ x) {
    int idx = blockIdx.x * blockDim.x + threadIdx.x;   // 4096*128 threads
    int row = idx >> 7;
    int kt = idx & 127;
    const float4* src = (const float4*)(x + (size_t)row * MCOLS + kt * 32);
    float v[32];
    #pragma unroll
    for (int i = 0; i < 8; ++i) {
        float4 t = src[i];
        v[i * 4 + 0] = t.x; v[i * 4 + 1] = t.y;
        v[i * 4 + 2] = t.z; v[i * 4 + 3] = t.w;
    }
    float4* dst = (float4*)(g_Xpack + (size_t)row * MCOLS + kt * 32);
    #pragma unroll
    for (int km = 0; km < 8; ++km) {
        uint32_t p[4];
        #pragma unroll
        for (int ks = 0; ks < 4; ++ks)
            asm("cvt.rna.tf32.f32 %0, %1;" : "=r"(p[ks]) : "f"(v[ks * 8 + km]));
        float4 o;
        o.x = __uint_as_float(p[0]); o.y = __uint_as_float(p[1]);
        o.z = __uint_as_float(p[2]); o.w = __uint_as_float(p[3]);
        dst[km] = o;
    }
}

__device__ __forceinline__ void cp16(uint32_t dst, const void* src) {
    asm volatile("cp.async.cg.shared.global [%0], [%1], 16;\n" :: "r"(dst), "l"(src));
}

__device__ __forceinline__ void load_stage(uint32_t sA, uint32_t sB,
                                           int m0, int n0, int kt, int buf, int tid) {
    const uint32_t base = (uint32_t)(buf * STAGE_FLOATS * 4);
    const int k0 = kt * BK;
    #pragma unroll
    for (int i = 0; i < 4; ++i) {
        int c = i * 256 + tid;     // 0..1023
        int row = c >> 3;          // 0..127
        int seg = c & 7;           // 8 x 16B per 32-float k-block
        uint32_t so = base + (uint32_t)(row * SROW + seg * 4) * 4;
        cp16(sA + so, g_Xpack + (size_t)(m0 + row) * MCOLS + k0 + seg * 4);
        cp16(sB + so, g_Wpack + (size_t)(n0 + row) * MCOLS + k0 + seg * 4);
    }
    asm volatile("cp.async.commit_group;\n" ::);
}

#define MMA(d, a0, a1, a2, a3, b0, b1)                                      \
    asm volatile(                                                           \
        "mma.sync.aligned.m16n8k8.row.col.f32.tf32.tf32.f32 "               \
        "{%0,%1,%2,%3}, {%4,%5,%6,%7}, {%8,%9}, {%0,%1,%2,%3};"             \
        : "+f"((d)[0]), "+f"((d)[1]), "+f"((d)[2]), "+f"((d)[3])            \
        : "r"(a0), "r"(a1), "r"(a2), "r"(a3), "r"(b0), "r"(b1))

__global__ void __launch_bounds__(256, 2)
sgemm_tf32(const float* __restrict__ bias, float* __restrict__ out) {
    extern __shared__ float smem[];
    float* As = smem;                   // [2][128][SROW]
    float* Bs = smem + TILE_FLOATS;     // [2][128][SROW] interleaved per stage

    const int tid  = threadIdx.x;
    const int lane = tid & 31;
    const int warp = tid >> 5;
    const int wm = (warp & 3) * 32;     // 4 warps in M
    const int wn = (warp >> 2) * 64;    // 2 warps in N
    const int qr = lane >> 2;           // 0..7
    const int km = lane & 3;            // km within fragment

    const int m0 = blockIdx.y * BM;
    const int n0 = blockIdx.x * BN;

    float acc[2][8][4];
    #pragma unroll
    for (int i = 0; i < 2; i++)
        #pragma unroll
        for (int j = 0; j < 8; j++)
            #pragma unroll
            for (int c = 0; c < 4; c++) acc[i][j][c] = 0.f;

    const uint32_t sA = (uint32_t)__cvta_generic_to_shared(As);
    const uint32_t sB = (uint32_t)__cvta_generic_to_shared(Bs);

    load_stage(sA, sB, m0, n0, 0, 0, tid);

    for (int kt = 0; kt < KSTEPS; ++kt) {
        const int cur = kt & 1;
        if (kt + 1 < KSTEPS) {
            load_stage(sA, sB, m0, n0, kt + 1, cur ^ 1, tid);
            asm volatile("cp.async.wait_group 1;\n" ::);
        } else {
            asm volatile("cp.async.wait_group 0;\n" ::);
        }
        __syncthreads();

        const float* Ac = As + cur * STAGE_FLOATS;
        const float* Bc = Bs + cur * STAGE_FLOATS;

        // A fragments: all 4 k-steps per LDS.128. va[mt][pos].{x,y,z,w} = ks 0..3
        // pos: 0=(r,km) 1=(r+8,km) 2=(r,km+4) 3=(r+8,km+4)
        uint4 va[2][4];
        #pragma unroll
        for (int mt = 0; mt < 2; ++mt) {
            const int r = wm + mt * 16 + qr;
            const float* p = Ac + r * SROW + km * 4;
            va[mt][0] = *(const uint4*)(p);
            va[mt][1] = *(const uint4*)(p + 8 * SROW);
            va[mt][2] = *(const uint4*)(p + 16);
            va[mt][3] = *(const uint4*)(p + 8 * SROW + 16);
        }

        #pragma unroll
        for (int nt = 0; nt < 8; ++nt) {
            const int n = wn + nt * 8 + qr;
            const float* p = Bc + n * SROW + km * 4;
            uint4 vb0 = *(const uint4*)(p);        // b0 for ks 0..3
            uint4 vb1 = *(const uint4*)(p + 16);   // b1 for ks 0..3
            #pragma unroll
            for (int mt = 0; mt < 2; ++mt) {
                MMA(acc[mt][nt], va[mt][0].x, va[mt][1].x, va[mt][2].x, va[mt][3].x, vb0.x, vb1.x);
                MMA(acc[mt][nt], va[mt][0].y, va[mt][1].y, va[mt][2].y, va[mt][3].y, vb0.y, vb1.y);
                MMA(acc[mt][nt], va[mt][0].z, va[mt][1].z, va[mt][2].z, va[mt][3].z, vb0.z, vb1.z);
                MMA(acc[mt][nt], va[mt][0].w, va[mt][1].w, va[mt][2].w, va[mt][3].w, vb0.w, vb1.w);
            }
        }
        __syncthreads();
    }

    // Epilogue: out[b][n] = acc + bias[n]
    #pragma unroll
    for (int mt = 0; mt < 2; ++mt) {
        const int rbase = m0 + wm + mt * 16 + qr;
        #pragma unroll
        for (int nt = 0; nt < 8; ++nt) {
            const int nbase = n0 + wn + nt * 8 + 2 * (lane & 3);
            const float b0 = bias[nbase];
            const float b1 = bias[nbase + 1];
            float2 v0 = make_float2(acc[mt][nt][0] + b0, acc[mt][nt][1] + b1);
            float2 v1 = make_float2(acc[mt][nt][2] + b0, acc[mt][nt][3] + b1);
            *(float2*)(out + (size_t)rbase * NROWS + nbase) = v0;
            *(float2*)(out + (size_t)(rbase + 8) * NROWS + nbase) = v1;
        }
    }
}

extern "C" void kernel_launch(void* const* d_in, const int* in_sizes, int n_in,
                              void* d_out, int out_size) {
    const float* x    = (const float*)d_in[0];
    const float* wval = (const float*)d_in[1];
    const float* bias = (const float*)d_in[2];
    const int*   rows = (const int*)d_in[3];
    const int*   cols = (const int*)d_in[4];
    float* out = (float*)d_out;

    scatter_kernel<<<(NNZ_TOTAL + 255) / 256, 256>>>(wval, rows, cols);
    pack_x_kernel<<<(BATCH * KSTEPS) / 256, 256>>>(x);

    cudaFuncSetAttribute(sgemm_tf32,
                         cudaFuncAttributeMaxDynamicSharedMemorySize, SMEM_BYTES);
    dim3 grid(NROWS / BN, BATCH / BM);
    sgemm_tf32<<<grid, 256, SMEM_BYTES>>>(bias, out);
}

// round 4
// speedup vs baseline: 1.0610x; 1.0610x over previous
#include <cuda_runtime.h>
#include <cstdint>

#define BATCH 4096
#define MCOLS 4096
#define NROWS 4096
#define NNZ_PER_ROW 819
#define NNZ_TOTAL (NROWS * NNZ_PER_ROW)

#define BM 128
#define BN 128
#define BK 32
#define KSTEPS (MCOLS / BK)        // 128
#define SROW 40                    // floats; 160B stride -> conflict-free LDS.64 (qr*8 words mod 32 distinct)
#define TILE_FLOATS (128 * SROW)   // 5120 floats (20KB) per matrix per stage
#define STAGE_FLOATS (2 * TILE_FLOATS)      // A+B per stage (40KB)
#define SMEM_BYTES (2 * STAGE_FLOATS * 4)   // double buffered = 81920 B

// Pair-packed tf32 buffers: within each 32-wide k-block, element k = ks*8 + j
// (ks in 0..3, j in 0..7) is stored at (ks>>1)*16 + j*2 + (ks&1), so one LDS.64
// yields a thread's operand for two consecutive k-steps.
// g_Wpack is zero-initialized at module load; scatter writes the same values to
// the same (fixed CSR) positions every call -> deterministic across replays.
__device__ float g_Wpack[(size_t)NROWS * MCOLS];
__device__ float g_Xpack[(size_t)BATCH * MCOLS];

__global__ void scatter_kernel(const float* __restrict__ val,
                               const int* __restrict__ rows,
                               const int* __restrict__ cols) {
    int i = blockIdx.x * blockDim.x + threadIdx.x;
    if (i < NNZ_TOTAL) {
        float v = val[i];
        uint32_t t;
        asm("cvt.rna.tf32.f32 %0, %1;" : "=r"(t) : "f"(v));
        uint32_t c = (uint32_t)cols[i];
        uint32_t w = c & 31u;
        uint32_t ks = w >> 3, j = w & 7u;
        uint32_t off = (c & ~31u) + (ks >> 1) * 16u + j * 2u + (ks & 1u);
        g_Wpack[(size_t)rows[i] * MCOLS + off] = __uint_as_float(t);
    }
}

// tf32-round + pair-permute x. One thread per (row, ktile).
__global__ void __launch_bounds__(256)
pack_x_kernel(const float* __restrict__ x) {
    int idx = blockIdx.x * blockDim.x + threadIdx.x;
    int row = idx >> 7;
    int kt = idx & 127;
    const float4* src = (const float4*)(x + (size_t)row * MCOLS + kt * 32);
    float v[32];
    #pragma unroll
    for (int i = 0; i < 8; ++i) {
        float4 t = src[i];
        v[i * 4 + 0] = t.x; v[i * 4 + 1] = t.y;
        v[i * 4 + 2] = t.z; v[i * 4 + 3] = t.w;
    }
    float o[32];
    #pragma unroll
    for (int ks = 0; ks < 4; ++ks)
        #pragma unroll
        for (int j = 0; j < 8; ++j) {
            uint32_t t;
            asm("cvt.rna.tf32.f32 %0, %1;" : "=r"(t) : "f"(v[ks * 8 + j]));
            o[(ks >> 1) * 16 + j * 2 + (ks & 1)] = __uint_as_float(t);
        }
    float4* dst = (float4*)(g_Xpack + (size_t)row * MCOLS + kt * 32);
    #pragma unroll
    for (int i = 0; i < 8; ++i)
        dst[i] = make_float4(o[i * 4], o[i * 4 + 1], o[i * 4 + 2], o[i * 4 + 3]);
}

__device__ __forceinline__ void cp16(uint32_t dst, const void* src) {
    asm volatile("cp.async.cg.shared.global [%0], [%1], 16;\n" :: "r"(dst), "l"(src));
}

__device__ __forceinline__ void load_stage(uint32_t sA, uint32_t sB,
                                           const float* __restrict__ gA,
                                           const float* __restrict__ gB,
                                           int buf) {
    const uint32_t base = (uint32_t)(buf * STAGE_FLOATS * 4);
    #pragma unroll
    for (int i = 0; i < 4; ++i) {
        // this thread's (row, seg) advances by 32 rows per iteration
        uint32_t so = base + (uint32_t)(i * 32 * SROW) * 4;
        cp16(sA + so, gA + (size_t)i * 32 * MCOLS);
        cp16(sB + so, gB + (size_t)i * 32 * MCOLS);
    }
    asm volatile("cp.async.commit_group;\n" ::);
}

#define MMA(d, a0, a1, a2, a3, b0, b1)                                      \
    asm volatile(                                                           \
        "mma.sync.aligned.m16n8k8.row.col.f32.tf32.tf32.f32 "               \
        "{%0,%1,%2,%3}, {%4,%5,%6,%7}, {%8,%9}, {%0,%1,%2,%3};"             \
        : "+f"((d)[0]), "+f"((d)[1]), "+f"((d)[2]), "+f"((d)[3])            \
        : "r"(a0), "r"(a1), "r"(a2), "r"(a3), "r"(b0), "r"(b1))

__global__ void __launch_bounds__(256, 2)
sgemm_tf32(const float* __restrict__ bias, float* __restrict__ out) {
    extern __shared__ float smem[];
    float* As = smem;                   // [2 stages][128][SROW]
    float* Bs = smem + TILE_FLOATS;

    const int tid  = threadIdx.x;
    const int lane = tid & 31;
    const int warp = tid >> 5;
    const int wm = (warp & 3) * 32;     // 4 warps in M
    const int wn = (warp >> 2) * 64;    // 2 warps in N
    const int qr = lane >> 2;           // group id 0..7
    const int tg = lane & 3;            // thread-in-group

    const int m0 = blockIdx.y * BM;
    const int n0 = blockIdx.x * BN;

    float acc[2][8][4];
    #pragma unroll
    for (int i = 0; i < 2; i++)
        #pragma unroll
        for (int j = 0; j < 8; j++)
            #pragma unroll
            for (int c = 0; c < 4; c++) acc[i][j][c] = 0.f;

    const uint32_t sAb = (uint32_t)__cvta_generic_to_shared(As);
    const uint32_t sBb = (uint32_t)__cvta_generic_to_shared(Bs);

    // per-thread fixed (row, seg) for the loader
    const int lrow = tid >> 3;          // 0..31
    const int lseg = tid & 7;           // 0..7 (16B segments)
    const uint32_t sA = sAb + (uint32_t)(lrow * SROW + lseg * 4) * 4;
    const uint32_t sB = sBb + (uint32_t)(lrow * SROW + lseg * 4) * 4;
    const float* gA = g_Xpack + (size_t)(m0 + lrow) * MCOLS + lseg * 4;
    const float* gB = g_Wpack + (size_t)(n0 + lrow) * MCOLS + lseg * 4;

    load_stage(sA, sB, gA, gB, 0);
    gA += BK; gB += BK;

    for (int kt = 0; kt < KSTEPS; ++kt) {
        const int cur = kt & 1;
        if (kt + 1 < KSTEPS) {
            load_stage(sA, sB, gA, gB, cur ^ 1);
            gA += BK; gB += BK;
            asm volatile("cp.async.wait_group 1;\n" ::);
        } else {
            asm volatile("cp.async.wait_group 0;\n" ::);
        }
        __syncthreads();

        const float* Ac = As + cur * STAGE_FLOATS;
        const float* Bc = Bs + cur * STAGE_FLOATS;

        #pragma unroll
        for (int h = 0; h < 2; ++h) {
            // A pair-fragments for this ks-half: .x = ks=2h, .y = ks=2h+1
            uint2 va[2][4];
            #pragma unroll
            for (int mt = 0; mt < 2; ++mt) {
                const float* p = Ac + (wm + mt * 16 + qr) * SROW + h * 16 + tg * 2;
                va[mt][0] = *(const uint2*)(p);                 // (qr,   tg)
                va[mt][1] = *(const uint2*)(p + 8 * SROW);      // (qr+8, tg)
                va[mt][2] = *(const uint2*)(p + 8);             // (qr,   tg+4)
                va[mt][3] = *(const uint2*)(p + 8 * SROW + 8);  // (qr+8, tg+4)
            }
            #pragma unroll
            for (int nt = 0; nt < 8; ++nt) {
                const float* q = Bc + (wn + nt * 8 + qr) * SROW + h * 16 + tg * 2;
                uint2 vb0 = *(const uint2*)(q);       // k=tg   for ks pair
                uint2 vb1 = *(const uint2*)(q + 8);   // k=tg+4 for ks pair
                #pragma unroll
                for (int mt = 0; mt < 2; ++mt) {
                    MMA(acc[mt][nt], va[mt][0].x, va[mt][1].x, va[mt][2].x, va[mt][3].x,
                        vb0.x, vb1.x);
                    MMA(acc[mt][nt], va[mt][0].y, va[mt][1].y, va[mt][2].y, va[mt][3].y,
                        vb0.y, vb1.y);
                }
            }
        }
        __syncthreads();
    }

    // Epilogue: out[b][n] = acc + bias[n]
    #pragma unroll
    for (int mt = 0; mt < 2; ++mt) {
        const int rbase = m0 + wm + mt * 16 + qr;
        #pragma unroll
        for (int nt = 0; nt < 8; ++nt) {
            const int nbase = n0 + wn + nt * 8 + 2 * tg;
            const float b0 = bias[nbase];
            const float b1 = bias[nbase + 1];
            float2 v0 = make_float2(acc[mt][nt][0] + b0, acc[mt][nt][1] + b1);
            float2 v1 = make_float2(acc[mt][nt][2] + b0, acc[mt][nt][3] + b1);
            *(float2*)(out + (size_t)rbase * NROWS + nbase) = v0;
            *(float2*)(out + (size_t)(rbase + 8) * NROWS + nbase) = v1;
        }
    }
}

extern "C" void kernel_launch(void* const* d_in, const int* in_sizes, int n_in,
                              void* d_out, int out_size) {
    const float* x    = (const float*)d_in[0];
    const float* wval = (const float*)d_in[1];
    const float* bias = (const float*)d_in[2];
    const int*   rows = (const int*)d_in[3];
    const int*   cols = (const int*)d_in[4];
    float* out = (float*)d_out;

    scatter_kernel<<<(NNZ_TOTAL + 255) / 256, 256>>>(wval, rows, cols);
    pack_x_kernel<<<(BATCH * KSTEPS) / 256, 256>>>(x);

    cudaFuncSetAttribute(sgemm_tf32,
                         cudaFuncAttributeMaxDynamicSharedMemorySize, SMEM_BYTES);
    dim3 grid(NROWS / BN, BATCH / BM);
    sgemm_tf32<<<grid, 256, SMEM_BYTES>>>(bias, out);
}